// round 7
// baseline (speedup 1.0000x reference)
#include <cuda_runtime.h>
#include <cstdint>
#include <cstddef>

// ---------------------------------------------------------------------------
// Decoder: LSTM(1 step, h0=c0=0) -> GCNConv -> ReLU -> GCNConv -> Linear+ReLU
// N=100000 nodes, L=H=O=128, E=1.6M edges (+ self loops)
//
// edge_index is INT32 on device (JAX x64-disabled downgrades the requested
// int64). R4 read it as int64 -> garbage indices -> illegal memory access.
//
// Normalization folding:
//   GCN out[i] = dinv[i] * ( sum_{e: dst=i} u[src_e] + u[i] ) + b
//   where u = (x @ W) * dinv (row-scaled in GEMM epilogue).
//   acc is SEEDED with u in the GEMM epilogue (self-loop term).
//
// Combine fusion: the node-wise transform relu?(dinv*acc + b) is applied in
// the NEXT GEMM's A-tile load (APRE template param) — no intermediate tensor
// between a conv's scatter and the next matmul.
//
// LSTM simplification: c0 = 0 => f-gate irrelevant. Only i, g, o computed.
// ---------------------------------------------------------------------------

#define MAX_N 100000

__device__ __align__(16) float g_gates[(size_t)MAX_N * 384];   // [i | g | o]
__device__ __align__(16) float g_h   [(size_t)MAX_N * 128];
__device__ __align__(16) float g_u   [(size_t)MAX_N * 128];
__device__ __align__(16) float g_acc [(size_t)MAX_N * 128];
__device__ __align__(16) float g_acc2[(size_t)MAX_N * 128];
__device__ __align__(16) float g_deg [MAX_N];
__device__ __align__(16) float g_dinv[MAX_N];

// ------------------------------ degree / dinv ------------------------------

__global__ void deg_init_kernel(float* deg, int N) {
    int i = blockIdx.x * blockDim.x + threadIdx.x;
    if (i < N) deg[i] = 1.0f;  // self-loop
}

__global__ void deg_scatter_kernel(const int* __restrict__ dst, float* deg, int E) {
    int e = blockIdx.x * blockDim.x + threadIdx.x;
    if (e < E) atomicAdd(&deg[dst[e]], 1.0f);
}

__global__ void dinv_kernel(const float* __restrict__ deg, float* dinv, int N) {
    int i = blockIdx.x * blockDim.x + threadIdx.x;
    if (i < N) dinv[i] = rsqrtf(deg[i]);
}

// ------------------------------ SGEMM (K = 128) ----------------------------
// C[N, Mout] = f(A)[N,128] @ B, 256 threads, BM=BN=128, BK=8, TM=TN=8.
// TRANSB=true:  B is [*,128] row-major (C = f(A) @ B^T slice)
// TRANSB=false: B is [128,M] row-major (C = f(A) @ B)
// GATES=true:   blockIdx.y in {0,1,2} selects W_ih row offset {0,256,384}
//               (i, g, o gates), output col block = blockIdx.y*128, Mout=384.
// APRE (A-prologue, f applied element-wise on A load, col index = k):
//      0 = identity
//      1 = relu(aScale[row]*a + aBias[k])
//      2 =      aScale[row]*a + aBias[k]
// EPI: 0 = none
//      1 = row-scale by scale[row], dual-write to C and C2 (acc seed)
//      2 = +bias[col] then ReLU

template<bool TRANSB, bool GATES, int APRE, int EPI>
__global__ __launch_bounds__(256, 2)
void sgemm_k128(const float* __restrict__ A, const float* __restrict__ B,
                float* __restrict__ C, float* __restrict__ C2, int N, int M,
                const float* __restrict__ scale, const float* __restrict__ bias,
                const float* __restrict__ aScale, const float* __restrict__ aBias) {
    constexpr int BM = 128, BN = 128, BK = 8, TM = 8, TN = 8;
    const int K = 128;

    __shared__ float As[BK][BM];
    __shared__ float Bs[BK][BN];

    const int tid = threadIdx.x;
    const int tr = tid / 16;          // 0..15 -> row group
    const int tc = tid % 16;          // 0..15 -> col group
    const int rowBase = blockIdx.x * BM;
    const int colBase = blockIdx.y * BN;                 // output col block
    // weight-row base for TRANSB loads (gate remap: 0 -> i, 1 -> g, 2 -> o)
    const int wBase = GATES ? ((blockIdx.y == 0) ? 0 : (int)(blockIdx.y + 1) * 128)
                            : colBase;

    float acc[TM][TN];
#pragma unroll
    for (int i = 0; i < TM; i++)
#pragma unroll
        for (int j = 0; j < TN; j++) acc[i][j] = 0.0f;

    // A-tile load indices: one float4 per thread per k-tile (256*4 = 128*8)
    const int aRow  = tid / 2;        // 0..127
    const int aCol4 = tid % 2;        // which float4 within the 8-wide k slab

    for (int kt = 0; kt < K; kt += BK) {
        // ---- load A (transposed into As), optional fused prologue ----
        {
            float4 av = make_float4(0.f, 0.f, 0.f, 0.f);
            int gRow = rowBase + aRow;
            if (gRow < N) {
                av = *(const float4*)(A + (size_t)gRow * K + kt + aCol4 * 4);
                if (APRE != 0) {
                    float s = aScale[gRow];
                    float4 bb = *(const float4*)(aBias + kt + aCol4 * 4);
                    av.x = s * av.x + bb.x;
                    av.y = s * av.y + bb.y;
                    av.z = s * av.z + bb.z;
                    av.w = s * av.w + bb.w;
                    if (APRE == 1) {
                        av.x = fmaxf(av.x, 0.f); av.y = fmaxf(av.y, 0.f);
                        av.z = fmaxf(av.z, 0.f); av.w = fmaxf(av.w, 0.f);
                    }
                }
            }
            As[aCol4 * 4 + 0][aRow] = av.x;
            As[aCol4 * 4 + 1][aRow] = av.y;
            As[aCol4 * 4 + 2][aRow] = av.z;
            As[aCol4 * 4 + 3][aRow] = av.w;
        }
        // ---- load B ----
        if (TRANSB) {
            int m  = tid / 2;
            int k4 = tid % 2;
            float4 bv = *(const float4*)(B + (size_t)(wBase + m) * K + kt + k4 * 4);
            Bs[k4 * 4 + 0][m] = bv.x;
            Bs[k4 * 4 + 1][m] = bv.y;
            Bs[k4 * 4 + 2][m] = bv.z;
            Bs[k4 * 4 + 3][m] = bv.w;
        } else {
            int k  = tid / 32;        // 0..7
            int m4 = tid % 32;        // 0..31 float4s across 128 cols
            float4 bv = *(const float4*)(B + (size_t)(kt + k) * M + colBase + m4 * 4);
            *(float4*)&Bs[k][m4 * 4] = bv;
        }
        __syncthreads();

#pragma unroll
        for (int k = 0; k < BK; k++) {
            float a[TM], b[TN];
            *(float4*)&a[0] = *(const float4*)&As[k][tr * TM];
            *(float4*)&a[4] = *(const float4*)&As[k][tr * TM + 4];
            *(float4*)&b[0] = *(const float4*)&Bs[k][tc * TN];
            *(float4*)&b[4] = *(const float4*)&Bs[k][tc * TN + 4];
#pragma unroll
            for (int i = 0; i < TM; i++)
#pragma unroll
                for (int j = 0; j < TN; j++)
                    acc[i][j] += a[i] * b[j];
        }
        __syncthreads();
    }

    // ---- epilogue ----
#pragma unroll
    for (int i = 0; i < TM; i++) {
        int gRow = rowBase + tr * TM + i;
        if (gRow >= N) continue;
        float rs = (EPI == 1) ? scale[gRow] : 1.0f;
#pragma unroll
        for (int j4 = 0; j4 < 2; j4++) {
            int gCol = colBase + tc * TN + j4 * 4;
            float4 v;
            v.x = acc[i][j4 * 4 + 0];
            v.y = acc[i][j4 * 4 + 1];
            v.z = acc[i][j4 * 4 + 2];
            v.w = acc[i][j4 * 4 + 3];
            if (EPI == 1) {
                v.x *= rs; v.y *= rs; v.z *= rs; v.w *= rs;
            } else if (EPI == 2) {
                v.x += bias[gCol + 0]; v.y += bias[gCol + 1];
                v.z += bias[gCol + 2]; v.w += bias[gCol + 3];
                v.x = fmaxf(v.x, 0.f); v.y = fmaxf(v.y, 0.f);
                v.z = fmaxf(v.z, 0.f); v.w = fmaxf(v.w, 0.f);
            }
            *(float4*)(C + (size_t)gRow * M + gCol) = v;
            if (EPI == 1)
                *(float4*)(C2 + (size_t)gRow * M + gCol) = v;  // acc seed (self-loop)
        }
    }
}

// ------------------------------ LSTM activation ----------------------------
// gates[N,384] laid out [i | g | o]; h = sigmoid(o)*tanh(sigmoid(i)*tanh(g))
// bias rows in original W_ih order: i->[0,128), g->[256,384), o->[384,512)

__device__ __forceinline__ float sigf(float x) { return 1.0f / (1.0f + expf(-x)); }

__global__ void lstm_act_kernel(const float* __restrict__ gates,
                                const float* __restrict__ b_ih,
                                const float* __restrict__ b_hh,
                                float* __restrict__ h, int N) {
    int idx = blockIdx.x * blockDim.x + threadIdx.x;
    if (idx >= N * 128) return;
    int n = idx >> 7;
    int j = idx & 127;
    const float* g = gates + (size_t)n * 384;
    float gi = g[j]       + b_ih[j]       + b_hh[j];
    float gg = g[128 + j] + b_ih[256 + j] + b_hh[256 + j];
    float go = g[256 + j] + b_ih[384 + j] + b_hh[384 + j];
    float c = sigf(gi) * tanhf(gg);
    h[idx] = sigf(go) * tanhf(c);
}

// ------------------------------ scatter ------------------------------------
// One warp per edge: lane l moves float4 l of the 128-float row.

__global__ void edge_scatter_kernel(const int* __restrict__ esrc,
                                    const int* __restrict__ edst,
                                    const float4* __restrict__ u,
                                    float* __restrict__ acc, int E) {
    int warp = (blockIdx.x * blockDim.x + threadIdx.x) >> 5;
    int lane = threadIdx.x & 31;
    if (warp >= E) return;
    int src = esrc[warp];
    int dst = edst[warp];
    float4 v = u[(size_t)src * 32 + lane];
    float* p = acc + (size_t)dst * 128 + lane * 4;
    asm volatile("red.global.add.v4.f32 [%0], {%1, %2, %3, %4};"
                 :: "l"(p), "f"(v.x), "f"(v.y), "f"(v.z), "f"(v.w)
                 : "memory");
}

// ------------------------------ host ---------------------------------------

extern "C" void kernel_launch(void* const* d_in, const int* in_sizes, int n_in,
                              void* d_out, int out_size) {
    const float* z    = (const float*)d_in[0];
    const int*   ei   = (const int*)d_in[1];     // int32 (see header note)
    const float* W_ih = (const float*)d_in[2];
    // d_in[3] = W_hh (unused: h0 = 0)
    const float* b_ih = (const float*)d_in[4];
    const float* b_hh = (const float*)d_in[5];
    const float* W1   = (const float*)d_in[6];
    const float* b1   = (const float*)d_in[7];
    const float* W2   = (const float*)d_in[8];
    const float* b2   = (const float*)d_in[9];
    const float* W3   = (const float*)d_in[10];
    const float* b3   = (const float*)d_in[11];

    const int N = in_sizes[0] / 128;
    const int E = in_sizes[1] / 2;
    const int* esrc = ei;
    const int* edst = ei + E;
    float* out = (float*)d_out;

    float *gates, *h, *u, *acc, *acc2, *deg, *dinv;
    cudaGetSymbolAddress((void**)&gates, g_gates);
    cudaGetSymbolAddress((void**)&h,     g_h);
    cudaGetSymbolAddress((void**)&u,     g_u);
    cudaGetSymbolAddress((void**)&acc,   g_acc);
    cudaGetSymbolAddress((void**)&acc2,  g_acc2);
    cudaGetSymbolAddress((void**)&deg,   g_deg);
    cudaGetSymbolAddress((void**)&dinv,  g_dinv);

    const int nb    = (N + 127) / 128;           // GEMM row blocks
    const int nElem = N * 128;
    const int ewB   = (E + 7) / 8;               // warp-per-edge blocks (8 warps/blk)

    // degree + dinv
    deg_init_kernel<<<(N + 255) / 256, 256>>>(deg, N);
    deg_scatter_kernel<<<(E + 255) / 256, 256>>>(edst, deg, E);
    dinv_kernel<<<(N + 255) / 256, 256>>>(deg, dinv, N);

    // LSTM: gates(i,g,o) = z @ W_ih^T rows {0,256,384}+128 ; h = act(gates + biases)
    sgemm_k128<true, true, 0, 0><<<dim3(nb, 3), 256>>>(
        z, W_ih, gates, nullptr, N, 384, nullptr, nullptr, nullptr, nullptr);
    lstm_act_kernel<<<(nElem + 255) / 256, 256>>>(gates, b_ih, b_hh, h, N);

    // GCN conv 1: u = acc = (h @ W1) * dinv ; scatter into acc
    sgemm_k128<false, false, 0, 1><<<dim3(nb, 1), 256>>>(
        h, W1, u, acc, N, 128, dinv, nullptr, nullptr, nullptr);
    edge_scatter_kernel<<<ewB, 256>>>(esrc, edst, (const float4*)u, acc, E);

    // GCN conv 2: x = relu(dinv*acc + b1) fused on A-load;
    //             u = acc2 = (x @ W2) * dinv ; scatter into acc2
    sgemm_k128<false, false, 1, 1><<<dim3(nb, 1), 256>>>(
        acc, W2, u, acc2, N, 128, dinv, nullptr, dinv, b1);
    edge_scatter_kernel<<<ewB, 256>>>(esrc, edst, (const float4*)u, acc2, E);

    // final: h2 = dinv*acc2 + b2 fused on A-load; out = relu(h2 @ W3^T + b3)
    sgemm_k128<true, false, 2, 2><<<dim3(nb, 1), 256>>>(
        acc2, W3, out, nullptr, N, 128, nullptr, b3, dinv, b2);
}

// round 13
// speedup vs baseline: 1.0076x; 1.0076x over previous
#include <cuda_runtime.h>
#include <cuda_bf16.h>
#include <cstdint>
#include <cstddef>

// ---------------------------------------------------------------------------
// Decoder: LSTM(1 step, h0=c0=0) -> GCNConv -> ReLU -> GCNConv -> Linear+ReLU
// N=100000, L=H=O=128, E=1.6M edges (+self loops). edge_index is INT32.
//
// R7 SIMT FP32 baseline: 1050.8us (GEMMs L1-bound, 44% fma).
// R11: tcgen05 rejected (harness PTX target sm_103, no 'a' features).
// R12: mma.sync bf16 split-3-term, rel_err 9.2e-2 — B fragment used
//      ldmatrix.trans, but [n][k]-staged B needs NON-trans (fragment == the
//      staged matrix). R13 fix: LDSM non-trans for B, same addresses.
//
// Norm folding: u = (x@W)*dinv in epilogue; acc seeded with u (self-loop);
// after edge scatter out = dinv*acc + b, fused into next GEMM's A prologue.
// LSTM: c0=0 => f-gate dead; only i,g,o computed.
// ---------------------------------------------------------------------------

#define MAX_N 100000

__device__ __align__(16) float g_gates[(size_t)MAX_N * 384];   // [i | g | o]
__device__ __align__(16) float g_h   [(size_t)MAX_N * 128];
__device__ __align__(16) float g_u   [(size_t)MAX_N * 128];
__device__ __align__(16) float g_acc [(size_t)MAX_N * 128];
__device__ __align__(16) float g_acc2[(size_t)MAX_N * 128];
__device__ __align__(16) float g_deg [MAX_N];
__device__ __align__(16) float g_dinv[MAX_N];

// ------------------------------ PTX helpers --------------------------------

__device__ __forceinline__ uint32_t smem_u32(const void* p) {
    uint32_t a;
    asm("{ .reg .u64 t; cvta.to.shared.u64 t, %1; cvt.u32.u64 %0, t; }"
        : "=r"(a) : "l"(p));
    return a;
}

#define LDSM_X4(r, addr)                                                        \
    asm volatile("ldmatrix.sync.aligned.m8n8.x4.shared.b16 {%0,%1,%2,%3}, [%4];" \
                 : "=r"((r)[0]), "=r"((r)[1]), "=r"((r)[2]), "=r"((r)[3])        \
                 : "r"(addr))

#define MMA_BF16(d, a, b0, b1)                                                  \
    asm volatile("mma.sync.aligned.m16n8k16.row.col.f32.bf16.bf16.f32 "          \
                 "{%0,%1,%2,%3}, {%4,%5,%6,%7}, {%8,%9}, {%0,%1,%2,%3};"         \
                 : "+f"((d)[0]), "+f"((d)[1]), "+f"((d)[2]), "+f"((d)[3])        \
                 : "r"((a)[0]), "r"((a)[1]), "r"((a)[2]), "r"((a)[3]),           \
                   "r"(b0), "r"(b1))

// split fp32x4 -> bf16 hi pair-packed + bf16 lo pair-packed
__device__ __forceinline__ void split4(float4 v, uint2& hi, uint2& lo) {
    __nv_bfloat162 h0 = __float22bfloat162_rn(make_float2(v.x, v.y));
    __nv_bfloat162 h1 = __float22bfloat162_rn(make_float2(v.z, v.w));
    float2 r0 = __bfloat1622float2(h0);
    float2 r1 = __bfloat1622float2(h1);
    __nv_bfloat162 l0 = __float22bfloat162_rn(make_float2(v.x - r0.x, v.y - r0.y));
    __nv_bfloat162 l1 = __float22bfloat162_rn(make_float2(v.z - r1.x, v.w - r1.y));
    hi = make_uint2(*(uint32_t*)&h0, *(uint32_t*)&h1);
    lo = make_uint2(*(uint32_t*)&l0, *(uint32_t*)&l1);
}

// ------------------------------ HMMA GEMM ----------------------------------
// C[N, Mout] = f(A)[N,128] @ op(B), CTA tile 128x128, K=128, 256 thr (8 warps,
// 4x2 warp grid; each warp 32 rows x 64 cols = 2 m-tiles x 8 n-tiles).
// Operands staged in smem as bf16 hi/lo, [row][k] with row stride 136 elems.
// Both A (rows=m) and B (rows=n) fragments load with NON-trans ldmatrix:
//   reg j = 8x8 matrix j; thread T gets (row=T/4, k=2*(T%4)+{0,1}) — exactly
//   the m16n8k16 A and B fragment layouts.
// TRANSB=true: B row-major [*,128] (C = f(A) @ B^T). false: B [128,M].
// GATES: blockIdx.y {0,1,2} -> W_ih row base {0,256,384}.
// APRE: 0 none; 1 relu(aScale[row]*a+aBias[k]); 2 aScale[row]*a+aBias[k].
// EPI:  0 none; 1 row-scale, dual write C,C2; 2 +bias[col], ReLU.

static constexpr int LDS_E = 136;                       // row stride, elements
static constexpr int MAT_E = 128 * LDS_E;               // elements per matrix
static constexpr int SMEM_TOTAL = 4 * MAT_E * 2;        // 139264 bytes

template<bool TRANSB, bool GATES, int APRE, int EPI>
__global__ __launch_bounds__(256)
void mma_gemm(const float* __restrict__ A, const float* __restrict__ B,
              float* __restrict__ C, float* __restrict__ C2, int N, int M,
              const float* __restrict__ scale, const float* __restrict__ bias,
              const float* __restrict__ aScale, const float* __restrict__ aBias) {
    extern __shared__ __nv_bfloat16 smem[];
    __nv_bfloat16* Ah = smem;
    __nv_bfloat16* Al = Ah + MAT_E;
    __nv_bfloat16* Bh = Al + MAT_E;
    __nv_bfloat16* Bl = Bh + MAT_E;

    const int tid = threadIdx.x;
    const int lane = tid & 31;
    const int warp = tid >> 5;
    const int warpM = warp & 3;          // 0..3 -> 32-row slab
    const int warpN = warp >> 2;         // 0..1 -> 64-col slab
    const int rowBase = blockIdx.x * 128;
    const int colBase = blockIdx.y * 128;
    const int wBase = GATES ? ((blockIdx.y == 0) ? 0 : (int)(blockIdx.y + 1) * 128)
                            : colBase;

    // ---- stage A (rows rowBase..), fused APRE, split hi/lo ----
    for (int it = tid; it < 128 * 32; it += 256) {
        int m  = it >> 5;
        int k4 = (it & 31) << 2;
        int gRow = rowBase + m;
        float4 av = make_float4(0.f, 0.f, 0.f, 0.f);
        if (gRow < N) {
            av = *(const float4*)(A + (size_t)gRow * 128 + k4);
            if (APRE != 0) {
                float s = aScale[gRow];
                float4 bb = *(const float4*)(aBias + k4);
                av.x = s * av.x + bb.x;  av.y = s * av.y + bb.y;
                av.z = s * av.z + bb.z;  av.w = s * av.w + bb.w;
                if (APRE == 1) {
                    av.x = fmaxf(av.x, 0.f); av.y = fmaxf(av.y, 0.f);
                    av.z = fmaxf(av.z, 0.f); av.w = fmaxf(av.w, 0.f);
                }
            }
        }
        uint2 hi, lo;  split4(av, hi, lo);
        *(uint2*)(Ah + m * LDS_E + k4) = hi;
        *(uint2*)(Al + m * LDS_E + k4) = lo;
    }

    // ---- stage B operand: rows = out-col (n), cols = k ----
    if (TRANSB) {
        for (int it = tid; it < 128 * 32; it += 256) {
            int m  = it >> 5;
            int k4 = (it & 31) << 2;
            float4 bv = *(const float4*)(B + (size_t)(wBase + m) * 128 + k4);
            uint2 hi, lo;  split4(bv, hi, lo);
            *(uint2*)(Bh + m * LDS_E + k4) = hi;
            *(uint2*)(Bl + m * LDS_E + k4) = lo;
        }
    } else {
        for (int it = tid; it < 128 * 32; it += 256) {
            int m  = it & 127;           // consecutive tid -> consecutive col (coalesced)
            int k4 = (it >> 7) << 2;
            float4 bv;
            bv.x = B[(size_t)(k4 + 0) * M + colBase + m];
            bv.y = B[(size_t)(k4 + 1) * M + colBase + m];
            bv.z = B[(size_t)(k4 + 2) * M + colBase + m];
            bv.w = B[(size_t)(k4 + 3) * M + colBase + m];
            uint2 hi, lo;  split4(bv, hi, lo);
            *(uint2*)(Bh + m * LDS_E + k4) = hi;
            *(uint2*)(Bl + m * LDS_E + k4) = lo;
        }
    }
    __syncthreads();

    // ---- mainloop: 8 k-steps of 16 ----
    float acc[2][8][4];
#pragma unroll
    for (int mt = 0; mt < 2; mt++)
#pragma unroll
        for (int nt = 0; nt < 8; nt++)
#pragma unroll
            for (int r = 0; r < 4; r++) acc[mt][nt][r] = 0.f;

    // A addr: lanes 0-15 rows 0-15 @k0; lanes 16-31 same rows @k0+8
    const int aRowIn = warpM * 32 + (lane & 15);
    const int aColIn = (lane >> 4) << 3;
    // B addr (NON-trans x4): matrices {n0-7,k0-7},{n0-7,k8-15},{n8-15,k0-7},{n8-15,k8-15}
    const int bRowIn = warpN * 64 + (lane & 7) + ((lane >> 4) << 3);
    const int bColIn = ((lane >> 3) & 1) << 3;

#pragma unroll
    for (int ks = 0; ks < 8; ks++) {
        const int k0 = ks * 16;
        uint32_t ah[2][4], al[2][4];
#pragma unroll
        for (int mt = 0; mt < 2; mt++) {
            uint32_t adr = smem_u32(Ah + (aRowIn + mt * 16) * LDS_E + k0 + aColIn);
            LDSM_X4(ah[mt], adr);
            adr = smem_u32(Al + (aRowIn + mt * 16) * LDS_E + k0 + aColIn);
            LDSM_X4(al[mt], adr);
        }
        uint32_t bh[4][4], bl[4][4];
#pragma unroll
        for (int nt2 = 0; nt2 < 4; nt2++) {
            uint32_t adr = smem_u32(Bh + (bRowIn + nt2 * 16) * LDS_E + k0 + bColIn);
            LDSM_X4(bh[nt2], adr);
            adr = smem_u32(Bl + (bRowIn + nt2 * 16) * LDS_E + k0 + bColIn);
            LDSM_X4(bl[nt2], adr);
        }
#pragma unroll
        for (int mt = 0; mt < 2; mt++) {
#pragma unroll
            for (int nt2 = 0; nt2 < 4; nt2++) {
                // regs [0],[1] = n-tile 2*nt2 (k0-7, k8-15); [2],[3] = n-tile 2*nt2+1
                MMA_BF16(acc[mt][2 * nt2 + 0], ah[mt], bh[nt2][0], bh[nt2][1]);
                MMA_BF16(acc[mt][2 * nt2 + 0], al[mt], bh[nt2][0], bh[nt2][1]);
                MMA_BF16(acc[mt][2 * nt2 + 0], ah[mt], bl[nt2][0], bl[nt2][1]);
                MMA_BF16(acc[mt][2 * nt2 + 1], ah[mt], bh[nt2][2], bh[nt2][3]);
                MMA_BF16(acc[mt][2 * nt2 + 1], al[mt], bh[nt2][2], bh[nt2][3]);
                MMA_BF16(acc[mt][2 * nt2 + 1], ah[mt], bl[nt2][2], bl[nt2][3]);
            }
        }
    }

    // ---- epilogue: thread holds rows (r, r+8), cols nt*8 + 2*(lane%4) ----
#pragma unroll
    for (int mt = 0; mt < 2; mt++) {
        int r0 = rowBase + warpM * 32 + mt * 16 + (lane >> 2);
        int r1 = r0 + 8;
        float rs0 = 1.f, rs1 = 1.f;
        if (EPI == 1) {
            if (r0 < N) rs0 = scale[r0];
            if (r1 < N) rs1 = scale[r1];
        }
#pragma unroll
        for (int nt = 0; nt < 8; nt++) {
            int gCol = colBase + warpN * 64 + nt * 8 + ((lane & 3) << 1);
            float2 v0 = make_float2(acc[mt][nt][0], acc[mt][nt][1]);
            float2 v1 = make_float2(acc[mt][nt][2], acc[mt][nt][3]);
            if (EPI == 1) {
                v0.x *= rs0; v0.y *= rs0;
                v1.x *= rs1; v1.y *= rs1;
            } else if (EPI == 2) {
                float b0 = bias[gCol], b1 = bias[gCol + 1];
                v0.x = fmaxf(v0.x + b0, 0.f); v0.y = fmaxf(v0.y + b1, 0.f);
                v1.x = fmaxf(v1.x + b0, 0.f); v1.y = fmaxf(v1.y + b1, 0.f);
            }
            if (r0 < N) {
                *(float2*)(C + (size_t)r0 * M + gCol) = v0;
                if (EPI == 1) *(float2*)(C2 + (size_t)r0 * M + gCol) = v0;
            }
            if (r1 < N) {
                *(float2*)(C + (size_t)r1 * M + gCol) = v1;
                if (EPI == 1) *(float2*)(C2 + (size_t)r1 * M + gCol) = v1;
            }
        }
    }
}

// ------------------------------ degree / dinv ------------------------------

__global__ void deg_init_kernel(float* deg, int N) {
    int i = blockIdx.x * blockDim.x + threadIdx.x;
    if (i < N) deg[i] = 1.0f;
}

__global__ void deg_scatter_kernel(const int* __restrict__ dst, float* deg, int E) {
    int e = blockIdx.x * blockDim.x + threadIdx.x;
    if (e < E) atomicAdd(&deg[dst[e]], 1.0f);
}

__global__ void dinv_kernel(const float* __restrict__ deg, float* dinv, int N) {
    int i = blockIdx.x * blockDim.x + threadIdx.x;
    if (i < N) dinv[i] = rsqrtf(deg[i]);
}

// ------------------------------ LSTM activation ----------------------------

__device__ __forceinline__ float sigf(float x) { return 1.0f / (1.0f + expf(-x)); }

__global__ void lstm_act_kernel(const float* __restrict__ gates,
                                const float* __restrict__ b_ih,
                                const float* __restrict__ b_hh,
                                float* __restrict__ h, int N) {
    int idx = blockIdx.x * blockDim.x + threadIdx.x;
    if (idx >= N * 128) return;
    int n = idx >> 7;
    int j = idx & 127;
    const float* g = gates + (size_t)n * 384;
    float gi = g[j]       + b_ih[j]       + b_hh[j];
    float gg = g[128 + j] + b_ih[256 + j] + b_hh[256 + j];
    float go = g[256 + j] + b_ih[384 + j] + b_hh[384 + j];
    float c = sigf(gi) * tanhf(gg);
    h[idx] = sigf(go) * tanhf(c);
}

// ------------------------------ scatter ------------------------------------

__global__ void edge_scatter_kernel(const int* __restrict__ esrc,
                                    const int* __restrict__ edst,
                                    const float4* __restrict__ u,
                                    float* __restrict__ acc, int E) {
    int warp = (blockIdx.x * blockDim.x + threadIdx.x) >> 5;
    int lane = threadIdx.x & 31;
    if (warp >= E) return;
    int src = esrc[warp];
    int dst = edst[warp];
    float4 v = u[(size_t)src * 32 + lane];
    float* p = acc + (size_t)dst * 128 + lane * 4;
    asm volatile("red.global.add.v4.f32 [%0], {%1, %2, %3, %4};"
                 :: "l"(p), "f"(v.x), "f"(v.y), "f"(v.z), "f"(v.w)
                 : "memory");
}

// ------------------------------ host ---------------------------------------

extern "C" void kernel_launch(void* const* d_in, const int* in_sizes, int n_in,
                              void* d_out, int out_size) {
    const float* z    = (const float*)d_in[0];
    const int*   ei   = (const int*)d_in[1];     // int32
    const float* W_ih = (const float*)d_in[2];
    // d_in[3] = W_hh (unused: h0 = 0)
    const float* b_ih = (const float*)d_in[4];
    const float* b_hh = (const float*)d_in[5];
    const float* W1   = (const float*)d_in[6];
    const float* b1   = (const float*)d_in[7];
    const float* W2   = (const float*)d_in[8];
    const float* b2   = (const float*)d_in[9];
    const float* W3   = (const float*)d_in[10];
    const float* b3   = (const float*)d_in[11];

    const int N = in_sizes[0] / 128;
    const int E = in_sizes[1] / 2;
    const int* esrc = ei;
    const int* edst = ei + E;
    float* out = (float*)d_out;

    float *gates, *h, *u, *acc, *acc2, *deg, *dinv;
    cudaGetSymbolAddress((void**)&gates, g_gates);
    cudaGetSymbolAddress((void**)&h,     g_h);
    cudaGetSymbolAddress((void**)&u,     g_u);
    cudaGetSymbolAddress((void**)&acc,   g_acc);
    cudaGetSymbolAddress((void**)&acc2,  g_acc2);
    cudaGetSymbolAddress((void**)&deg,   g_deg);
    cudaGetSymbolAddress((void**)&dinv,  g_dinv);

    // opt-in to 136KB dynamic smem (idempotent, capture-safe attribute set)
    cudaFuncSetAttribute(mma_gemm<true,  true,  0, 0>, cudaFuncAttributeMaxDynamicSharedMemorySize, SMEM_TOTAL);
    cudaFuncSetAttribute(mma_gemm<false, false, 0, 1>, cudaFuncAttributeMaxDynamicSharedMemorySize, SMEM_TOTAL);
    cudaFuncSetAttribute(mma_gemm<false, false, 1, 1>, cudaFuncAttributeMaxDynamicSharedMemorySize, SMEM_TOTAL);
    cudaFuncSetAttribute(mma_gemm<true,  false, 2, 2>, cudaFuncAttributeMaxDynamicSharedMemorySize, SMEM_TOTAL);

    const int nb    = (N + 127) / 128;
    const int nElem = N * 128;
    const int ewB   = (E + 7) / 8;

    // degree + dinv
    deg_init_kernel<<<(N + 255) / 256, 256>>>(deg, N);
    deg_scatter_kernel<<<(E + 255) / 256, 256>>>(edst, deg, E);
    dinv_kernel<<<(N + 255) / 256, 256>>>(deg, dinv, N);

    // LSTM: gates(i,g,o) = z @ W_ih^T ; h = act(gates + biases)
    mma_gemm<true, true, 0, 0><<<dim3(nb, 3), 256, SMEM_TOTAL>>>(
        z, W_ih, gates, nullptr, N, 384, nullptr, nullptr, nullptr, nullptr);
    lstm_act_kernel<<<(nElem + 255) / 256, 256>>>(gates, b_ih, b_hh, h, N);

    // GCN conv 1: u = acc = (h @ W1) * dinv ; scatter into acc
    mma_gemm<false, false, 0, 1><<<dim3(nb, 1), 256, SMEM_TOTAL>>>(
        h, W1, u, acc, N, 128, dinv, nullptr, nullptr, nullptr);
    edge_scatter_kernel<<<ewB, 256>>>(esrc, edst, (const float4*)u, acc, E);

    // GCN conv 2: x = relu(dinv*acc + b1) fused on A-load;
    //             u = acc2 = (x @ W2) * dinv ; scatter into acc2
    mma_gemm<false, false, 1, 1><<<dim3(nb, 1), 256, SMEM_TOTAL>>>(
        acc, W2, u, acc2, N, 128, dinv, nullptr, dinv, b1);
    edge_scatter_kernel<<<ewB, 256>>>(esrc, edst, (const float4*)u, acc2, E);

    // final: h2 = dinv*acc2 + b2 fused on A-load; out = relu(h2 @ W3^T + b3)
    mma_gemm<true, false, 2, 2><<<dim3(nb, 1), 256, SMEM_TOTAL>>>(
        acc2, W3, out, nullptr, N, 128, nullptr, b3, dinv, b2);
}